// round 8
// baseline (speedup 1.0000x reference)
#include <cuda_runtime.h>
#include <cuda_fp16.h>
#include <stdint.h>

#define B_SZ     4096
#define D0       1024
#define D1       8192
#define D2       8192
#define D3       10240
#define NNEUR    (D1 + D2 + D3)     // 26624
#define KCLS     10
#define GRP      (D3 / KCLS)        // 1024
#define TAU      30.0f
#define ROWS     4
#define NTHREADS 1024
#define NWARP    (NTHREADS / 32)    // 32
#define CELLS    256                // 16 a-bank-pairs x 16 b-bank-pairs
#define CHUNK    1024
#define CAP      (CHUNK / CELLS)    // 4

// -------- staging (original order) --------
__device__ uint32_t s_idx[NNEUR];
__device__ uint32_t s_c01[NNEUR];
__device__ uint32_t s_c23[NNEUR];
// -------- permutations (layer-local) + final metadata (dealt positions) ----
__device__ uint16_t d_perm1[D1], d_inv1[D1];   // perm: pos->orig, inv: orig->pos
__device__ uint16_t d_perm2[D2], d_inv2[D2];
__device__ uint16_t d_perm3[D3];               // within-group position perm
__device__ uint32_t g_idx[NNEUR];              // ia | (ib<<16), position-space
__device__ uint2    g_coef[NNEUR];             // {half2(c0,c1), half2(c2,c3)}

__constant__ float OPC[16][4] = {
    {0.f, 0.f, 0.f, 0.f}, {0.f, 0.f, 0.f, 1.f}, {0.f, 1.f, 0.f, -1.f}, {0.f, 1.f, 0.f, 0.f},
    {0.f, 0.f, 1.f, -1.f}, {0.f, 0.f, 1.f, 0.f}, {0.f, 1.f, 1.f, -2.f}, {0.f, 1.f, 1.f, -1.f},
    {1.f, -1.f, -1.f, 1.f}, {1.f, -1.f, -1.f, 2.f}, {1.f, 0.f, -1.f, 0.f}, {1.f, 0.f, -1.f, 1.f},
    {1.f, -1.f, 0.f, 0.f}, {1.f, -1.f, 0.f, 1.f}, {1.f, 0.f, 0.f, -1.f}, {1.f, 0.f, 0.f, 0.f}};

__global__ void precompute_kernel(
    const float* __restrict__ w1, const float* __restrict__ w2, const float* __restrict__ w3,
    const int* __restrict__ ia1, const int* __restrict__ ib1,
    const int* __restrict__ ia2, const int* __restrict__ ib2,
    const int* __restrict__ ia3, const int* __restrict__ ib3)
{
    int j = blockIdx.x * blockDim.x + threadIdx.x;
    if (j >= NNEUR) return;
    const float* w; int ia, ib;
    if (j < D1)            { w = w1 + (size_t)j * 16;               ia = ia1[j];            ib = ib1[j]; }
    else if (j < D1 + D2)  { int k = j - D1;      w = w2 + (size_t)k * 16; ia = ia2[k]; ib = ib2[k]; }
    else                   { int k = j - D1 - D2; w = w3 + (size_t)k * 16; ia = ia3[k]; ib = ib3[k]; }

    float v[16]; float m = -3.4e38f;
#pragma unroll
    for (int i = 0; i < 16; i++) { v[i] = w[i]; m = fmaxf(m, v[i]); }
    float s = 0.f;
#pragma unroll
    for (int i = 0; i < 16; i++) { v[i] = expf(v[i] - m); s += v[i]; }
    float inv = 1.f / s;
    float c0 = 0.f, c1 = 0.f, c2 = 0.f, c3 = 0.f;
#pragma unroll
    for (int i = 0; i < 16; i++) {
        float p = v[i] * inv;
        c0 = fmaf(p, OPC[i][0], c0);
        c1 = fmaf(p, OPC[i][1], c1);
        c2 = fmaf(p, OPC[i][2], c2);
        c3 = fmaf(p, OPC[i][3], c3);
    }
    s_idx[j] = (uint32_t)ia | ((uint32_t)ib << 16);
    __half2 h01 = __floats2half2_rn(c0, c1);
    __half2 h23 = __floats2half2_rn(c2, c3);
    s_c01[j] = *reinterpret_cast<uint32_t*>(&h01);
    s_c23[j] = *reinterpret_cast<uint32_t*>(&h23);
}

// ---- bank-deal builder: one CTA per 1024-neuron chunk (R7-validated core) --
// Produces a POSITION permutation within the chunk such that each aligned
// 32-slot warp window has every a-bank-pair exactly 2x and every b-bank-pair
// exactly 2x (conflict-free LDS.64 gathers), modulo Poisson leftovers.
// Deterministic: __match_any ranks + warp-shuffle scans. No atomics.
__global__ void __launch_bounds__(1024, 1)
build_deal_kernel(int layerBase, const uint16_t* __restrict__ remap,
                  uint16_t* __restrict__ perm, uint16_t* __restrict__ inv)
{
    constexpr int SCNSTR = 40;                    // 32 warps + pad
    __shared__ uint16_t off[CELLS * SCNSTR];
    __shared__ uint16_t chbase[CELLS * 4];
    __shared__ uint16_t csize[CELLS], exoff[CELLS], ufoff[CELLS];
    __shared__ uint16_t ufp[CHUNK];
    __shared__ int wte[8], wtu[8];

    const int tid  = threadIdx.x;
    const int lane = tid & 31;
    const int w    = tid >> 5;
    const uint32_t ltm = (1u << lane) - 1u;
    const int baseL = blockIdx.x * CHUNK;         // layer-local chunk base

    for (int i = tid; i < CELLS * SCNSTR / 2; i += 1024)
        reinterpret_cast<uint32_t*>(off)[i] = 0;
    __syncthreads();

    uint32_t pk = s_idx[layerBase + baseL + tid];
    uint32_t a = pk & 0xffffu, b = pk >> 16;
    if (remap) { a = remap[a]; b = remap[b]; }
    int cell = (int)((a & 15u) * 16u + (b & 15u));
    uint32_t mask = __match_any_sync(0xffffffffu, cell);
    int lr = __popc(mask & ltm);
    if ((mask & ltm) == 0)
        off[cell * SCNSTR + w] = (uint16_t)__popc(mask);
    __syncthreads();

    {   // phase 1: per-(cell, 8-warp chunk) exclusive scan
        int c  = tid >> 2;
        int ch = tid & 3;
        int bo = c * SCNSTR + ch * 8;
        uint16_t run = 0;
#pragma unroll
        for (int i = 0; i < 8; i++) {
            uint16_t t = off[bo + i];
            off[bo + i] = run;
            run = (uint16_t)(run + t);
        }
        chbase[c * 4 + ch] = run;
    }
    __syncthreads();

    if (tid < CELLS) {   // phase 2: per-cell combine
        int c = tid; uint16_t bb = 0;
#pragma unroll
        for (int ch = 0; ch < 4; ch++) {
            uint16_t t = chbase[c * 4 + ch];
            chbase[c * 4 + ch] = bb;
            bb = (uint16_t)(bb + t);
        }
        csize[c] = bb;
        exoff[c] = (bb > CAP) ? (uint16_t)(bb - CAP) : 0;
        ufoff[c] = (bb < CAP) ? (uint16_t)(CAP - bb) : 0;
    }
    __syncthreads();

    // inclusive scans over 256 cells via warp shuffles
    int e = 0, u = 0;
    if (tid < CELLS) {
        e = exoff[tid]; u = ufoff[tid];
#pragma unroll
        for (int o = 1; o < 32; o <<= 1) {
            int pe = __shfl_up_sync(0xffffffffu, e, o);
            int pu = __shfl_up_sync(0xffffffffu, u, o);
            if (lane >= o) { e += pe; u += pu; }
        }
        if (lane == 31) { wte[w] = e; wtu[w] = u; }
    }
    __syncthreads();
    if (tid == 0) {
        int be = 0, bu = 0;
#pragma unroll
        for (int i = 0; i < 8; i++) {
            int te = wte[i], tu = wtu[i];
            wte[i] = be; wtu[i] = bu;
            be += te; bu += tu;
        }
    }
    __syncthreads();
    if (tid < CELLS) {
        exoff[tid] = (uint16_t)(e + wte[w]);
        ufoff[tid] = (uint16_t)(u + wtu[w]);
    }
    __syncthreads();

    if (tid < CELLS) {   // emit unfilled dealt positions, grouped by cell
        int c = tid, t = c >> 4, s = c & 15;
        int sz  = csize[c];
        int ufc = (sz < CAP) ? CAP - sz : 0;
        int ub  = ufoff[c] - ufc;
        for (int m = sz; m < CAP; m++)
            ufp[ub + (m - sz)] = (uint16_t)((((s - t) & 15) + 16 * m) * 16 + t);
    }
    __syncthreads();

    {   // assign positions
        int grank = off[cell * SCNSTR + w] + chbase[cell * 4 + (w >> 3)] + lr;
        int t = cell >> 4, s = cell & 15;
        int p;
        if (grank < CAP) {
            p = (((s - t) & 15) + 16 * grank) * 16 + t;
        } else {
            int exc = csize[cell] - CAP;
            int exb = exoff[cell] - exc;
            p = ufp[exb + (grank - CAP)];
        }
        perm[baseL + p] = (uint16_t)(baseL + tid);
        if (inv) inv[baseL + tid] = (uint16_t)(baseL + p);
    }
}

// ---- merge: permuted positions + remapped indices -------------------------
__global__ void merge_meta_kernel()
{
    int s = blockIdx.x * blockDim.x + threadIdx.x;
    if (s >= NNEUR) return;
    if (s < D1) {
        int o = d_perm1[s];                       // layer-local orig
        g_idx[s]  = s_idx[o];                     // x is unpermuted
        g_coef[s] = make_uint2(s_c01[o], s_c23[o]);
    } else if (s < D1 + D2) {
        int o = d_perm2[s - D1];
        uint32_t pk = s_idx[D1 + o];
        uint32_t a = d_inv1[pk & 0xffffu], b = d_inv1[pk >> 16];
        g_idx[s]  = a | (b << 16);
        g_coef[s] = make_uint2(s_c01[D1 + o], s_c23[D1 + o]);
    } else {
        int o = d_perm3[s - D1 - D2];             // within-group (chunk==group)
        uint32_t pk = s_idx[D1 + D2 + o];
        uint32_t a = d_inv2[pk & 0xffffu], b = d_inv2[pk >> 16];
        g_idx[s]  = a | (b << 16);
        g_coef[s] = make_uint2(s_c01[D1 + D2 + o], s_c23[D1 + D2 + o]);
    }
}

// -------- main kernel: R3 structure (coalesced stores), dealt gathers -------

struct NeuronIn {
    uint32_t pk, u01, u23;
    uint2 a, b;
};

__device__ __forceinline__ void fetch_neuron(const uint2* __restrict__ src,
                                             int mj, NeuronIn& n)
{
    n.pk = __ldg(&g_idx[mj]);
    uint2 cc = __ldg(&g_coef[mj]);
    n.u01 = cc.x;
    n.u23 = cc.y;
    n.a = src[n.pk & 0xffffu];
    n.b = src[n.pk >> 16];
}

__device__ __forceinline__ uint2 neuron_math(const NeuronIn& n)
{
    float2 c01 = __half22float2(*reinterpret_cast<const __half2*>(&n.u01));
    float2 c23 = __half22float2(*reinterpret_cast<const __half2*>(&n.u23));
    uint2 o;
#pragma unroll
    for (int r = 0; r < 2; r++) {
        uint32_t ua = (r == 0) ? n.a.x : n.a.y;
        uint32_t ub = (r == 0) ? n.b.x : n.b.y;
        float2 a = __half22float2(*reinterpret_cast<const __half2*>(&ua));
        float2 b = __half22float2(*reinterpret_cast<const __half2*>(&ub));
        float o0 = fmaf(fmaf(c23.y, b.x, c01.y), a.x, fmaf(c23.x, b.x, c01.x));
        float o1 = fmaf(fmaf(c23.y, b.y, c01.y), a.y, fmaf(c23.x, b.y, c01.x));
        __half2 h = __floats2half2_rn(o0, o1);
        uint32_t uh = *reinterpret_cast<uint32_t*>(&h);
        if (r == 0) o.x = uh; else o.y = uh;
    }
    return o;
}

__device__ __forceinline__ void run_layer(const uint2* __restrict__ src,
                                          uint2* __restrict__ dst,
                                          int metaBase, int D, int tid)
{
    const int iters = D / NTHREADS;
    NeuronIn cur, nxt;
    int j = tid;
    fetch_neuron(src, metaBase + j, cur);
#pragma unroll 2
    for (int it = 0; it < iters - 1; it++) {
        fetch_neuron(src, metaBase + j + NTHREADS, nxt);
        dst[j] = neuron_math(cur);
        cur = nxt;
        j += NTHREADS;
    }
    dst[j] = neuron_math(cur);
}

__global__ void __launch_bounds__(NTHREADS, 1)
diff_logic_main(const float* __restrict__ x, float* __restrict__ out)
{
    extern __shared__ __align__(16) uint32_t smem_raw[];
    uint2* xs = reinterpret_cast<uint2*>(smem_raw);
    uint2* h1 = xs + D0;
    uint2* h2 = h1 + D1;
    float* wacc = reinterpret_cast<float*>(h2 + D2);

    const int tid  = threadIdx.x;
    const int row0 = blockIdx.x * ROWS;

    {
        int col = tid;                            // D0 == NTHREADS
        float v0 = x[(size_t)(row0 + 0) * D0 + col];
        float v1 = x[(size_t)(row0 + 1) * D0 + col];
        float v2 = x[(size_t)(row0 + 2) * D0 + col];
        float v3 = x[(size_t)(row0 + 3) * D0 + col];
        __half2 p0 = __floats2half2_rn(v0, v1);
        __half2 p1 = __floats2half2_rn(v2, v3);
        uint2 slot;
        slot.x = *reinterpret_cast<uint32_t*>(&p0);
        slot.y = *reinterpret_cast<uint32_t*>(&p1);
        xs[col] = slot;
    }
    __syncthreads();

    run_layer(xs, h1, 0, D1, tid);
    __syncthreads();
    run_layer(h1, h2, D1, D2, tid);
    __syncthreads();

    // Layer 3 fused with group-sum (position perm stays within each group).
    const int lane = tid & 31;
    const int warp = tid >> 5;

    for (int g = 0; g < KCLS; g++) {
        float acc[ROWS];
#pragma unroll
        for (int r = 0; r < ROWS; r++) acc[r] = 0.f;
        {
            int mj = D1 + D2 + g * GRP + tid;     // GRP == NTHREADS
            NeuronIn n;
            fetch_neuron(h2, mj, n);
            float2 c01 = __half22float2(*reinterpret_cast<const __half2*>(&n.u01));
            float2 c23 = __half22float2(*reinterpret_cast<const __half2*>(&n.u23));
#pragma unroll
            for (int r = 0; r < 2; r++) {
                uint32_t ua = (r == 0) ? n.a.x : n.a.y;
                uint32_t ub = (r == 0) ? n.b.x : n.b.y;
                float2 a = __half22float2(*reinterpret_cast<const __half2*>(&ua));
                float2 b = __half22float2(*reinterpret_cast<const __half2*>(&ub));
                acc[2 * r + 0] = fmaf(fmaf(c23.y, b.x, c01.y), a.x, fmaf(c23.x, b.x, c01.x));
                acc[2 * r + 1] = fmaf(fmaf(c23.y, b.y, c01.y), a.y, fmaf(c23.x, b.y, c01.x));
            }
        }
#pragma unroll
        for (int r = 0; r < ROWS; r++) {
#pragma unroll
            for (int off = 16; off > 0; off >>= 1)
                acc[r] += __shfl_down_sync(0xffffffffu, acc[r], off);
        }
        if (lane == 0) {
#pragma unroll
            for (int r = 0; r < ROWS; r++)
                wacc[(g * NWARP + warp) * ROWS + r] = acc[r];
        }
    }
    __syncthreads();

    if (tid < KCLS * ROWS) {
        int g = tid / ROWS;
        int r = tid - g * ROWS;
        float s = 0.f;
#pragma unroll
        for (int w = 0; w < NWARP; w++)
            s += wacc[(g * NWARP + w) * ROWS + r];
        out[(size_t)(row0 + r) * KCLS + g] = s * (1.f / TAU);
    }
}

// -----------------------------------------------------------------------------

extern "C" void kernel_launch(void* const* d_in, const int* in_sizes, int n_in,
                              void* d_out, int out_size)
{
    (void)in_sizes; (void)n_in; (void)out_size;
    const float* x  = (const float*)d_in[0];
    const float* w1 = (const float*)d_in[1];
    const float* w2 = (const float*)d_in[2];
    const float* w3 = (const float*)d_in[3];
    const int* ia1 = (const int*)d_in[4];
    const int* ib1 = (const int*)d_in[5];
    const int* ia2 = (const int*)d_in[6];
    const int* ib2 = (const int*)d_in[7];
    const int* ia3 = (const int*)d_in[8];
    const int* ib3 = (const int*)d_in[9];
    float* out = (float*)d_out;

    precompute_kernel<<<(NNEUR + 255) / 256, 256>>>(w1, w2, w3, ia1, ib1, ia2, ib2, ia3, ib3);

    uint16_t *perm1, *inv1, *perm2, *inv2, *perm3;
    cudaGetSymbolAddress((void**)&perm1, d_perm1);
    cudaGetSymbolAddress((void**)&inv1,  d_inv1);
    cudaGetSymbolAddress((void**)&perm2, d_perm2);
    cudaGetSymbolAddress((void**)&inv2,  d_inv2);
    cudaGetSymbolAddress((void**)&perm3, d_perm3);

    build_deal_kernel<<<D1 / CHUNK, 1024>>>(0,       nullptr, perm1, inv1);
    build_deal_kernel<<<D2 / CHUNK, 1024>>>(D1,      inv1,    perm2, inv2);
    build_deal_kernel<<<D3 / CHUNK, 1024>>>(D1 + D2, inv2,    perm3, nullptr);
    merge_meta_kernel<<<(NNEUR + 255) / 256, 256>>>();

    size_t smem = (size_t)(D0 + D1 + D2) * sizeof(uint2)
                + (size_t)(KCLS * NWARP * ROWS) * sizeof(float);   // 144,384 B
    cudaFuncSetAttribute(diff_logic_main, cudaFuncAttributeMaxDynamicSharedMemorySize, (int)smem);

    diff_logic_main<<<B_SZ / ROWS, NTHREADS, smem>>>(x, out);
}

// round 9
// speedup vs baseline: 1.0120x; 1.0120x over previous
#include <cuda_runtime.h>
#include <cuda_fp16.h>
#include <stdint.h>

#define B_SZ     4096
#define D0       1024
#define D1       8192
#define D2       8192
#define D3       10240
#define NNEUR    (D1 + D2 + D3)     // 26624
#define KCLS     10
#define GRP      (D3 / KCLS)        // 1024
#define TAU      30.0f
#define ROWS     4
#define NTHREADS 1024
#define NWARP    (NTHREADS / 32)    // 32
#define CELLS    256                // 16 a-bank-pairs x 16 b-bank-pairs
#define CHUNK    1024
#define CAP      (CHUNK / CELLS)    // 4
#define NCHUNK   (NNEUR / CHUNK)    // 26

// -------- staging (original order) --------
__device__ uint32_t s_idx[NNEUR];
__device__ uint32_t s_c01[NNEUR];
__device__ uint32_t s_c23[NNEUR];
// -------- inverse perms (orig -> dealt pos, layer-local) + stage flags ------
__device__ uint16_t d_inv1[D1];
__device__ uint16_t d_inv2[D2];
__device__ int      d_stage_cnt[2];            // #chunks done for L1, L2
// -------- final metadata (dealt positions) --------
__device__ uint32_t g_idx[NNEUR];              // ia | (ib<<16), position-space
__device__ uint2    g_coef[NNEUR];             // {half2(c0,c1), half2(c2,c3)}

__constant__ float OPC[16][4] = {
    {0.f, 0.f, 0.f, 0.f}, {0.f, 0.f, 0.f, 1.f}, {0.f, 1.f, 0.f, -1.f}, {0.f, 1.f, 0.f, 0.f},
    {0.f, 0.f, 1.f, -1.f}, {0.f, 0.f, 1.f, 0.f}, {0.f, 1.f, 1.f, -2.f}, {0.f, 1.f, 1.f, -1.f},
    {1.f, -1.f, -1.f, 1.f}, {1.f, -1.f, -1.f, 2.f}, {1.f, 0.f, -1.f, 0.f}, {1.f, 0.f, -1.f, 1.f},
    {1.f, -1.f, 0.f, 0.f}, {1.f, -1.f, 0.f, 1.f}, {1.f, 0.f, 0.f, -1.f}, {1.f, 0.f, 0.f, 0.f}};

__global__ void precompute_kernel(
    const float* __restrict__ w1, const float* __restrict__ w2, const float* __restrict__ w3,
    const int* __restrict__ ia1, const int* __restrict__ ib1,
    const int* __restrict__ ia2, const int* __restrict__ ib2,
    const int* __restrict__ ia3, const int* __restrict__ ib3)
{
    int j = blockIdx.x * blockDim.x + threadIdx.x;
    if (j == 0) { d_stage_cnt[0] = 0; d_stage_cnt[1] = 0; }   // reset for this replay
    if (j >= NNEUR) return;
    const float* w; int ia, ib;
    if (j < D1)            { w = w1 + (size_t)j * 16;               ia = ia1[j];            ib = ib1[j]; }
    else if (j < D1 + D2)  { int k = j - D1;      w = w2 + (size_t)k * 16; ia = ia2[k]; ib = ib2[k]; }
    else                   { int k = j - D1 - D2; w = w3 + (size_t)k * 16; ia = ia3[k]; ib = ib3[k]; }

    float v[16]; float m = -3.4e38f;
#pragma unroll
    for (int i = 0; i < 16; i++) { v[i] = w[i]; m = fmaxf(m, v[i]); }
    float s = 0.f;
#pragma unroll
    for (int i = 0; i < 16; i++) { v[i] = expf(v[i] - m); s += v[i]; }
    float inv = 1.f / s;
    float c0 = 0.f, c1 = 0.f, c2 = 0.f, c3 = 0.f;
#pragma unroll
    for (int i = 0; i < 16; i++) {
        float p = v[i] * inv;
        c0 = fmaf(p, OPC[i][0], c0);
        c1 = fmaf(p, OPC[i][1], c1);
        c2 = fmaf(p, OPC[i][2], c2);
        c3 = fmaf(p, OPC[i][3], c3);
    }
    s_idx[j] = (uint32_t)ia | ((uint32_t)ib << 16);
    __half2 h01 = __floats2half2_rn(c0, c1);
    __half2 h23 = __floats2half2_rn(c2, c3);
    s_c01[j] = *reinterpret_cast<uint32_t*>(&h01);
    s_c23[j] = *reinterpret_cast<uint32_t*>(&h23);
}

// ---- fused bank-deal builder: 26 CTAs, one per 1024-neuron chunk -----------
// Layer-2/3 chunks spin-wait on the previous layer's completion counter
// (all 26 CTAs are co-resident: grid << #SM). Merge is folded in: each thread
// writes its own neuron's remapped metadata at its dealt position.
// Deal core: R8-validated (__match_any ranks + warp-shuffle scans, no atomics
// in the ranking; deterministic).
__global__ void __launch_bounds__(1024, 1)
fused_build_kernel()
{
    constexpr int SCNSTR = 40;                    // 32 warps + pad
    __shared__ uint16_t off[CELLS * SCNSTR];
    __shared__ uint16_t chbase[CELLS * 4];
    __shared__ uint16_t csize[CELLS], exoff[CELLS], ufoff[CELLS];
    __shared__ uint16_t ufp[CHUNK];
    __shared__ int wte[8], wtu[8];

    const int tid  = threadIdx.x;
    const int lane = tid & 31;
    const int w    = tid >> 5;
    const uint32_t ltm = (1u << lane) - 1u;

    const int chunk = blockIdx.x;
    const int layer = (chunk < 8) ? 0 : ((chunk < 16) ? 1 : 2);
    const int layerBase = (layer == 0) ? 0 : ((layer == 1) ? D1 : (D1 + D2));
    const int baseL = (chunk - ((layer == 0) ? 0 : ((layer == 1) ? 8 : 16))) * CHUNK;
    const int gj = layerBase + baseL + tid;       // this thread's neuron (orig order)

    // zero count table while (possibly) waiting
    for (int i = tid; i < CELLS * SCNSTR / 2; i += 1024)
        reinterpret_cast<uint32_t*>(off)[i] = 0;

    // load own staged metadata
    uint32_t pk  = s_idx[gj];
    uint32_t c01 = s_c01[gj];
    uint32_t c23 = s_c23[gj];

    // wait for previous layer's inv to be fully published
    if (layer > 0) {
        if (tid == 0) {
            volatile int* cnt = &d_stage_cnt[layer - 1];
            while (*cnt < 8) { }
        }
        __syncthreads();
        __threadfence();
    } else {
        __syncthreads();
    }

    // remap indices into previous layer's dealt position space
    uint32_t a = pk & 0xffffu, b = pk >> 16;
    if (layer == 1) { a = d_inv1[a]; b = d_inv1[b]; }
    else if (layer == 2) { a = d_inv2[a]; b = d_inv2[b]; }
    pk = a | (b << 16);

    // ---- deal ----
    int cell = (int)((a & 15u) * 16u + (b & 15u));
    uint32_t mask = __match_any_sync(0xffffffffu, cell);
    int lr = __popc(mask & ltm);
    if ((mask & ltm) == 0)
        off[cell * SCNSTR + w] = (uint16_t)__popc(mask);
    __syncthreads();

    {   // phase 1: per-(cell, 8-warp chunk) exclusive scan
        int c  = tid >> 2;
        int ch = tid & 3;
        int bo = c * SCNSTR + ch * 8;
        uint16_t run = 0;
#pragma unroll
        for (int i = 0; i < 8; i++) {
            uint16_t t = off[bo + i];
            off[bo + i] = run;
            run = (uint16_t)(run + t);
        }
        chbase[c * 4 + ch] = run;
    }
    __syncthreads();

    if (tid < CELLS) {   // phase 2: per-cell combine
        int c = tid; uint16_t bb = 0;
#pragma unroll
        for (int ch = 0; ch < 4; ch++) {
            uint16_t t = chbase[c * 4 + ch];
            chbase[c * 4 + ch] = bb;
            bb = (uint16_t)(bb + t);
        }
        csize[c] = bb;
        exoff[c] = (bb > CAP) ? (uint16_t)(bb - CAP) : 0;
        ufoff[c] = (bb < CAP) ? (uint16_t)(CAP - bb) : 0;
    }
    __syncthreads();

    // inclusive scans over 256 cells via warp shuffles
    {
        int e = 0, u = 0;
        if (tid < CELLS) {
            e = exoff[tid]; u = ufoff[tid];
#pragma unroll
            for (int o = 1; o < 32; o <<= 1) {
                int pe = __shfl_up_sync(0xffffffffu, e, o);
                int pu = __shfl_up_sync(0xffffffffu, u, o);
                if (lane >= o) { e += pe; u += pu; }
            }
            if (lane == 31) { wte[w] = e; wtu[w] = u; }
        }
        __syncthreads();
        if (tid == 0) {
            int be = 0, bu = 0;
#pragma unroll
            for (int i = 0; i < 8; i++) {
                int te = wte[i], tu = wtu[i];
                wte[i] = be; wtu[i] = bu;
                be += te; bu += tu;
            }
        }
        __syncthreads();
        if (tid < CELLS) {
            exoff[tid] = (uint16_t)(e + wte[w]);
            ufoff[tid] = (uint16_t)(u + wtu[w]);
        }
    }
    __syncthreads();

    if (tid < CELLS) {   // emit unfilled dealt positions, grouped by cell
        int c = tid, t = c >> 4, s = c & 15;
        int sz  = csize[c];
        int ufc = (sz < CAP) ? CAP - sz : 0;
        int ub  = ufoff[c] - ufc;
        for (int m = sz; m < CAP; m++)
            ufp[ub + (m - sz)] = (uint16_t)((((s - t) & 15) + 16 * m) * 16 + t);
    }
    __syncthreads();

    // assign position + merged metadata write
    {
        int grank = off[cell * SCNSTR + w] + chbase[cell * 4 + (w >> 3)] + lr;
        int t = cell >> 4, s = cell & 15;
        int p;
        if (grank < CAP) {
            p = (((s - t) & 15) + 16 * grank) * 16 + t;
        } else {
            int exc = csize[cell] - CAP;
            int exb = exoff[cell] - exc;
            p = ufp[exb + (grank - CAP)];
        }
        int dstPos = layerBase + baseL + p;
        g_idx[dstPos]  = pk;                      // already remapped
        g_coef[dstPos] = make_uint2(c01, c23);
        if (layer == 0)      d_inv1[baseL + tid] = (uint16_t)(baseL + p);
        else if (layer == 1) d_inv2[baseL + tid] = (uint16_t)(baseL + p);
    }

    // publish completion
    if (layer < 2) {
        __threadfence();
        __syncthreads();
        if (tid == 0) atomicAdd(&d_stage_cnt[layer], 1);
    }
}

// -------- main kernel: R3 structure (coalesced stores), dealt gathers -------

struct NeuronIn {
    uint32_t pk, u01, u23;
    uint2 a, b;
};

__device__ __forceinline__ void fetch_neuron(const uint2* __restrict__ src,
                                             int mj, NeuronIn& n)
{
    n.pk = __ldg(&g_idx[mj]);
    uint2 cc = __ldg(&g_coef[mj]);
    n.u01 = cc.x;
    n.u23 = cc.y;
    n.a = src[n.pk & 0xffffu];
    n.b = src[n.pk >> 16];
}

__device__ __forceinline__ uint2 neuron_math(const NeuronIn& n)
{
    float2 c01 = __half22float2(*reinterpret_cast<const __half2*>(&n.u01));
    float2 c23 = __half22float2(*reinterpret_cast<const __half2*>(&n.u23));
    uint2 o;
#pragma unroll
    for (int r = 0; r < 2; r++) {
        uint32_t ua = (r == 0) ? n.a.x : n.a.y;
        uint32_t ub = (r == 0) ? n.b.x : n.b.y;
        float2 a = __half22float2(*reinterpret_cast<const __half2*>(&ua));
        float2 b = __half22float2(*reinterpret_cast<const __half2*>(&ub));
        float o0 = fmaf(fmaf(c23.y, b.x, c01.y), a.x, fmaf(c23.x, b.x, c01.x));
        float o1 = fmaf(fmaf(c23.y, b.y, c01.y), a.y, fmaf(c23.x, b.y, c01.x));
        __half2 h = __floats2half2_rn(o0, o1);
        uint32_t uh = *reinterpret_cast<uint32_t*>(&h);
        if (r == 0) o.x = uh; else o.y = uh;
    }
    return o;
}

__device__ __forceinline__ void run_layer(const uint2* __restrict__ src,
                                          uint2* __restrict__ dst,
                                          int metaBase, int D, int tid)
{
    const int iters = D / NTHREADS;
    NeuronIn cur, nxt;
    int j = tid;
    fetch_neuron(src, metaBase + j, cur);
#pragma unroll 2
    for (int it = 0; it < iters - 1; it++) {
        fetch_neuron(src, metaBase + j + NTHREADS, nxt);
        dst[j] = neuron_math(cur);
        cur = nxt;
        j += NTHREADS;
    }
    dst[j] = neuron_math(cur);
}

__global__ void __launch_bounds__(NTHREADS, 1)
diff_logic_main(const float* __restrict__ x, float* __restrict__ out)
{
    extern __shared__ __align__(16) uint32_t smem_raw[];
    uint2* xs = reinterpret_cast<uint2*>(smem_raw);
    uint2* h1 = xs + D0;
    uint2* h2 = h1 + D1;
    float* wacc = reinterpret_cast<float*>(h2 + D2);

    const int tid  = threadIdx.x;
    const int row0 = blockIdx.x * ROWS;

    {
        int col = tid;                            // D0 == NTHREADS
        float v0 = x[(size_t)(row0 + 0) * D0 + col];
        float v1 = x[(size_t)(row0 + 1) * D0 + col];
        float v2 = x[(size_t)(row0 + 2) * D0 + col];
        float v3 = x[(size_t)(row0 + 3) * D0 + col];
        __half2 p0 = __floats2half2_rn(v0, v1);
        __half2 p1 = __floats2half2_rn(v2, v3);
        uint2 slot;
        slot.x = *reinterpret_cast<uint32_t*>(&p0);
        slot.y = *reinterpret_cast<uint32_t*>(&p1);
        xs[col] = slot;
    }
    __syncthreads();

    run_layer(xs, h1, 0, D1, tid);
    __syncthreads();
    run_layer(h1, h2, D1, D2, tid);
    __syncthreads();

    // Layer 3 fused with group-sum (position perm stays within each group).
    const int lane = tid & 31;
    const int warp = tid >> 5;

    for (int g = 0; g < KCLS; g++) {
        float acc[ROWS];
#pragma unroll
        for (int r = 0; r < ROWS; r++) acc[r] = 0.f;
        {
            int mj = D1 + D2 + g * GRP + tid;     // GRP == NTHREADS
            NeuronIn n;
            fetch_neuron(h2, mj, n);
            float2 c01 = __half22float2(*reinterpret_cast<const __half2*>(&n.u01));
            float2 c23 = __half22float2(*reinterpret_cast<const __half2*>(&n.u23));
#pragma unroll
            for (int r = 0; r < 2; r++) {
                uint32_t ua = (r == 0) ? n.a.x : n.a.y;
                uint32_t ub = (r == 0) ? n.b.x : n.b.y;
                float2 a = __half22float2(*reinterpret_cast<const __half2*>(&ua));
                float2 b = __half22float2(*reinterpret_cast<const __half2*>(&ub));
                acc[2 * r + 0] = fmaf(fmaf(c23.y, b.x, c01.y), a.x, fmaf(c23.x, b.x, c01.x));
                acc[2 * r + 1] = fmaf(fmaf(c23.y, b.y, c01.y), a.y, fmaf(c23.x, b.y, c01.x));
            }
        }
#pragma unroll
        for (int r = 0; r < ROWS; r++) {
#pragma unroll
            for (int off = 16; off > 0; off >>= 1)
                acc[r] += __shfl_down_sync(0xffffffffu, acc[r], off);
        }
        if (lane == 0) {
#pragma unroll
            for (int r = 0; r < ROWS; r++)
                wacc[(g * NWARP + warp) * ROWS + r] = acc[r];
        }
    }
    __syncthreads();

    if (tid < KCLS * ROWS) {
        int g = tid / ROWS;
        int r = tid - g * ROWS;
        float s = 0.f;
#pragma unroll
        for (int w = 0; w < NWARP; w++)
            s += wacc[(g * NWARP + w) * ROWS + r];
        out[(size_t)(row0 + r) * KCLS + g] = s * (1.f / TAU);
    }
}

// -----------------------------------------------------------------------------

extern "C" void kernel_launch(void* const* d_in, const int* in_sizes, int n_in,
                              void* d_out, int out_size)
{
    (void)in_sizes; (void)n_in; (void)out_size;
    const float* x  = (const float*)d_in[0];
    const float* w1 = (const float*)d_in[1];
    const float* w2 = (const float*)d_in[2];
    const float* w3 = (const float*)d_in[3];
    const int* ia1 = (const int*)d_in[4];
    const int* ib1 = (const int*)d_in[5];
    const int* ia2 = (const int*)d_in[6];
    const int* ib2 = (const int*)d_in[7];
    const int* ia3 = (const int*)d_in[8];
    const int* ib3 = (const int*)d_in[9];
    float* out = (float*)d_out;

    precompute_kernel<<<(NNEUR + 255) / 256, 256>>>(w1, w2, w3, ia1, ib1, ia2, ib2, ia3, ib3);
    fused_build_kernel<<<NCHUNK, 1024>>>();       // 26 co-resident CTAs, staged via flags

    size_t smem = (size_t)(D0 + D1 + D2) * sizeof(uint2)
                + (size_t)(KCLS * NWARP * ROWS) * sizeof(float);   // 144,384 B
    cudaFuncSetAttribute(diff_logic_main, cudaFuncAttributeMaxDynamicSharedMemorySize, (int)smem);

    diff_logic_main<<<B_SZ / ROWS, NTHREADS, smem>>>(x, out);
}

// round 11
// speedup vs baseline: 1.0324x; 1.0202x over previous
#include <cuda_runtime.h>
#include <cuda_fp16.h>
#include <stdint.h>

#define B_SZ     4096
#define D0       1024
#define D1       8192
#define D2       8192
#define D3       10240
#define NNEUR    (D1 + D2 + D3)     // 26624
#define KCLS     10
#define GRP      (D3 / KCLS)        // 1024
#define TAU      30.0f
#define ROWS     4
#define NTHREADS 1024
#define NWARP    (NTHREADS / 32)    // 32
#define CELLS    256                // 16 a-bank-pairs x 16 b-bank-pairs
#define CHUNK    1024
#define CAP      (CHUNK / CELLS)    // 4
#define NCHUNK   (NNEUR / CHUNK)    // 26
#define SCNSTR   40                 // 32 warps + pad

// -------- staging (original order) --------
__device__ uint32_t s_idx[NNEUR];
__device__ uint32_t s_c01[NNEUR];
__device__ uint32_t s_c23[NNEUR];
// -------- inverse perms + per-layer completion counters --------
__device__ uint16_t d_inv1[D1];
__device__ uint16_t d_inv2[D2];
__device__ int      d_stage_cnt[3];            // #chunks done for L1, L2, L3
// -------- final metadata (dealt positions) --------
__device__ uint32_t g_idx[NNEUR];              // ia | (ib<<16), position-space
__device__ uint2    g_coef[NNEUR];             // {half2(c0,c1), half2(c2,c3)}

__constant__ float OPC[16][4] = {
    {0.f, 0.f, 0.f, 0.f}, {0.f, 0.f, 0.f, 1.f}, {0.f, 1.f, 0.f, -1.f}, {0.f, 1.f, 0.f, 0.f},
    {0.f, 0.f, 1.f, -1.f}, {0.f, 0.f, 1.f, 0.f}, {0.f, 1.f, 1.f, -2.f}, {0.f, 1.f, 1.f, -1.f},
    {1.f, -1.f, -1.f, 1.f}, {1.f, -1.f, -1.f, 2.f}, {1.f, 0.f, -1.f, 0.f}, {1.f, 0.f, -1.f, 1.f},
    {1.f, -1.f, 0.f, 0.f}, {1.f, -1.f, 0.f, 1.f}, {1.f, 0.f, 0.f, -1.f}, {1.f, 0.f, 0.f, 0.f}};

__global__ void precompute_kernel(
    const float* __restrict__ w1, const float* __restrict__ w2, const float* __restrict__ w3,
    const int* __restrict__ ia1, const int* __restrict__ ib1,
    const int* __restrict__ ia2, const int* __restrict__ ib2,
    const int* __restrict__ ia3, const int* __restrict__ ib3)
{
    int j = blockIdx.x * blockDim.x + threadIdx.x;
    if (j < 3) d_stage_cnt[j] = 0;               // reset flags for this replay
    if (j >= NNEUR) return;
    const float* w; int ia, ib;
    if (j < D1)            { w = w1 + (size_t)j * 16;               ia = ia1[j];            ib = ib1[j]; }
    else if (j < D1 + D2)  { int k = j - D1;      w = w2 + (size_t)k * 16; ia = ia2[k]; ib = ib2[k]; }
    else                   { int k = j - D1 - D2; w = w3 + (size_t)k * 16; ia = ia3[k]; ib = ib3[k]; }

    float v[16]; float m = -3.4e38f;
#pragma unroll
    for (int i = 0; i < 16; i++) { v[i] = w[i]; m = fmaxf(m, v[i]); }
    float s = 0.f;
#pragma unroll
    for (int i = 0; i < 16; i++) { v[i] = expf(v[i] - m); s += v[i]; }
    float inv = 1.f / s;
    float c0 = 0.f, c1 = 0.f, c2 = 0.f, c3 = 0.f;
#pragma unroll
    for (int i = 0; i < 16; i++) {
        float p = v[i] * inv;
        c0 = fmaf(p, OPC[i][0], c0);
        c1 = fmaf(p, OPC[i][1], c1);
        c2 = fmaf(p, OPC[i][2], c2);
        c3 = fmaf(p, OPC[i][3], c3);
    }
    s_idx[j] = (uint32_t)ia | ((uint32_t)ib << 16);
    __half2 h01 = __floats2half2_rn(c0, c1);
    __half2 h23 = __floats2half2_rn(c2, c3);
    s_c01[j] = *reinterpret_cast<uint32_t*>(&h01);
    s_c23[j] = *reinterpret_cast<uint32_t*>(&h23);
}

// ---- acquire-poll on a stage counter (thread 0), then CTA barrier ----------
__device__ __forceinline__ void wait_stage(int idx, int target)
{
    if (threadIdx.x == 0) {
        int v;
        do {
            asm volatile("ld.acquire.gpu.global.b32 %0, [%1];"
                         : "=r"(v) : "l"(&d_stage_cnt[idx]) : "memory");
        } while (v < target);
    }
    __syncthreads();
}

// ---- bank-deal builder, run by CTAs 0..25 of the MAIN kernel ---------------
// Scratch lives in the h1 smem region (unused until layer-1 compute).
// Deal core: R8/R9-validated. Deterministic.
__device__ void do_build(int chunk, uint16_t* scratch)
{
    uint16_t* off    = scratch;                          // CELLS*SCNSTR
    uint16_t* chbase = off + CELLS * SCNSTR;             // CELLS*4
    uint16_t* csize  = chbase + CELLS * 4;               // CELLS
    uint16_t* exoff  = csize + CELLS;                    // CELLS
    uint16_t* ufoff  = exoff + CELLS;                    // CELLS
    uint16_t* ufp    = ufoff + CELLS;                    // CHUNK
    int* wte = reinterpret_cast<int*>(ufp + CHUNK);      // 8
    int* wtu = wte + 8;                                  // 8

    const int tid  = threadIdx.x;
    const int lane = tid & 31;
    const int w    = tid >> 5;
    const uint32_t ltm = (1u << lane) - 1u;

    const int layer = (chunk < 8) ? 0 : ((chunk < 16) ? 1 : 2);
    const int layerBase = (layer == 0) ? 0 : ((layer == 1) ? D1 : (D1 + D2));
    const int baseL = (chunk - ((layer == 0) ? 0 : ((layer == 1) ? 8 : 16))) * CHUNK;
    const int gj = layerBase + baseL + tid;

    for (int i = tid; i < CELLS * SCNSTR / 2; i += NTHREADS)
        reinterpret_cast<uint32_t*>(off)[i] = 0;

    uint32_t pk  = s_idx[gj];
    uint32_t c01 = s_c01[gj];
    uint32_t c23 = s_c23[gj];

    if (layer > 0) {
        wait_stage(layer - 1, 8);                        // prev layer's inv published
    } else {
        __syncthreads();
    }

    uint32_t a = pk & 0xffffu, b = pk >> 16;
    if (layer == 1) { a = d_inv1[a]; b = d_inv1[b]; }
    else if (layer == 2) { a = d_inv2[a]; b = d_inv2[b]; }
    pk = a | (b << 16);

    int cell = (int)((a & 15u) * 16u + (b & 15u));
    uint32_t mask = __match_any_sync(0xffffffffu, cell);
    int lr = __popc(mask & ltm);
    if ((mask & ltm) == 0)
        off[cell * SCNSTR + w] = (uint16_t)__popc(mask);
    __syncthreads();

    {   // phase 1: per-(cell, 8-warp chunk) exclusive scan
        int c  = tid >> 2;
        int ch = tid & 3;
        int bo = c * SCNSTR + ch * 8;
        uint16_t run = 0;
#pragma unroll
        for (int i = 0; i < 8; i++) {
            uint16_t t = off[bo + i];
            off[bo + i] = run;
            run = (uint16_t)(run + t);
        }
        chbase[c * 4 + ch] = run;
    }
    __syncthreads();

    if (tid < CELLS) {   // phase 2: per-cell combine
        int c = tid; uint16_t bb = 0;
#pragma unroll
        for (int ch = 0; ch < 4; ch++) {
            uint16_t t = chbase[c * 4 + ch];
            chbase[c * 4 + ch] = bb;
            bb = (uint16_t)(bb + t);
        }
        csize[c] = bb;
        exoff[c] = (bb > CAP) ? (uint16_t)(bb - CAP) : 0;
        ufoff[c] = (bb < CAP) ? (uint16_t)(CAP - bb) : 0;
    }
    __syncthreads();

    {   // inclusive scans over 256 cells via warp shuffles
        int e = 0, u = 0;
        if (tid < CELLS) {
            e = exoff[tid]; u = ufoff[tid];
#pragma unroll
            for (int o = 1; o < 32; o <<= 1) {
                int pe = __shfl_up_sync(0xffffffffu, e, o);
                int pu = __shfl_up_sync(0xffffffffu, u, o);
                if (lane >= o) { e += pe; u += pu; }
            }
            if (lane == 31) { wte[w] = e; wtu[w] = u; }
        }
        __syncthreads();
        if (tid == 0) {
            int be = 0, bu = 0;
#pragma unroll
            for (int i = 0; i < 8; i++) {
                int te = wte[i], tu = wtu[i];
                wte[i] = be; wtu[i] = bu;
                be += te; bu += tu;
            }
        }
        __syncthreads();
        if (tid < CELLS) {
            exoff[tid] = (uint16_t)(e + wte[w]);
            ufoff[tid] = (uint16_t)(u + wtu[w]);
        }
    }
    __syncthreads();

    if (tid < CELLS) {   // emit unfilled dealt positions, grouped by cell
        int c = tid, t = c >> 4, s = c & 15;
        int sz  = csize[c];
        int ufc = (sz < CAP) ? CAP - sz : 0;
        int ub  = ufoff[c] - ufc;
        for (int m = sz; m < CAP; m++)
            ufp[ub + (m - sz)] = (uint16_t)((((s - t) & 15) + 16 * m) * 16 + t);
    }
    __syncthreads();

    {   // assign position + merged metadata write
        int grank = off[cell * SCNSTR + w] + chbase[cell * 4 + (w >> 3)] + lr;
        int t = cell >> 4, s = cell & 15;
        int p;
        if (grank < CAP) {
            p = (((s - t) & 15) + 16 * grank) * 16 + t;
        } else {
            int exc = csize[cell] - CAP;
            int exb = exoff[cell] - exc;
            p = ufp[exb + (grank - CAP)];
        }
        int dstPos = layerBase + baseL + p;
        g_idx[dstPos]  = pk;
        g_coef[dstPos] = make_uint2(c01, c23);
        if (layer == 0)      d_inv1[baseL + tid] = (uint16_t)(baseL + p);
        else if (layer == 1) d_inv2[baseL + tid] = (uint16_t)(baseL + p);
    }

    __threadfence();
    __syncthreads();
    if (tid == 0) atomicAdd(&d_stage_cnt[layer], 1);
    __syncthreads();
}

// -------- main kernel -------------------------------------------------------

struct NeuronIn {
    uint32_t pk, u01, u23;
    uint2 a, b;
};

// NOTE: metadata is produced in THIS kernel by the builder CTAs, so these
// loads must be coherent (plain ld.global) — NOT __ldg/ld.global.nc, whose
// "read-only for the kernel lifetime" contract the builders violate (this
// exact bug cost R10 its correctness).
__device__ __forceinline__ void fetch_neuron(const uint2* __restrict__ src,
                                             int mj, NeuronIn& n)
{
    n.pk = g_idx[mj];
    uint2 cc = g_coef[mj];
    n.u01 = cc.x;
    n.u23 = cc.y;
    n.a = src[n.pk & 0xffffu];
    n.b = src[n.pk >> 16];
}

__device__ __forceinline__ uint2 neuron_math(const NeuronIn& n)
{
    float2 c01 = __half22float2(*reinterpret_cast<const __half2*>(&n.u01));
    float2 c23 = __half22float2(*reinterpret_cast<const __half2*>(&n.u23));
    uint2 o;
#pragma unroll
    for (int r = 0; r < 2; r++) {
        uint32_t ua = (r == 0) ? n.a.x : n.a.y;
        uint32_t ub = (r == 0) ? n.b.x : n.b.y;
        float2 a = __half22float2(*reinterpret_cast<const __half2*>(&ua));
        float2 b = __half22float2(*reinterpret_cast<const __half2*>(&ub));
        float o0 = fmaf(fmaf(c23.y, b.x, c01.y), a.x, fmaf(c23.x, b.x, c01.x));
        float o1 = fmaf(fmaf(c23.y, b.y, c01.y), a.y, fmaf(c23.x, b.y, c01.x));
        __half2 h = __floats2half2_rn(o0, o1);
        uint32_t uh = *reinterpret_cast<uint32_t*>(&h);
        if (r == 0) o.x = uh; else o.y = uh;
    }
    return o;
}

__device__ __forceinline__ void run_layer(const uint2* __restrict__ src,
                                          uint2* __restrict__ dst,
                                          int metaBase, int D, int tid)
{
    const int iters = D / NTHREADS;
    NeuronIn cur, nxt;
    int j = tid;
    fetch_neuron(src, metaBase + j, cur);
#pragma unroll 2
    for (int it = 0; it < iters - 1; it++) {
        fetch_neuron(src, metaBase + j + NTHREADS, nxt);
        dst[j] = neuron_math(cur);
        cur = nxt;
        j += NTHREADS;
    }
    dst[j] = neuron_math(cur);
}

__global__ void __launch_bounds__(NTHREADS, 1)
diff_logic_main(const float* __restrict__ x, float* __restrict__ out)
{
    extern __shared__ __align__(16) uint32_t smem_raw[];
    uint2* xs = reinterpret_cast<uint2*>(smem_raw);
    uint2* h1 = xs + D0;
    uint2* h2 = h1 + D1;
    float* wacc = reinterpret_cast<float*>(h2 + D2);

    const int tid  = threadIdx.x;
    const int bid  = blockIdx.x;
    const int row0 = bid * ROWS;

    {
        int col = tid;                            // D0 == NTHREADS
        float v0 = x[(size_t)(row0 + 0) * D0 + col];
        float v1 = x[(size_t)(row0 + 1) * D0 + col];
        float v2 = x[(size_t)(row0 + 2) * D0 + col];
        float v3 = x[(size_t)(row0 + 3) * D0 + col];
        __half2 p0 = __floats2half2_rn(v0, v1);
        __half2 p1 = __floats2half2_rn(v2, v3);
        uint2 slot;
        slot.x = *reinterpret_cast<uint32_t*>(&p0);
        slot.y = *reinterpret_cast<uint32_t*>(&p1);
        xs[col] = slot;
    }
    __syncthreads();

    // First NCHUNK CTAs build the dealt metadata (scratch aliased into h1,
    // which is rewritten in full by run_layer afterwards). All 26 builders
    // are wave-1 resident (grid=1024, 1 CTA/SM), so the stage chain makes
    // progress; later waves see the flags already set.
    if (bid < NCHUNK)
        do_build(bid, reinterpret_cast<uint16_t*>(h1));

    wait_stage(0, 8);
    run_layer(xs, h1, 0, D1, tid);
    __syncthreads();

    wait_stage(1, 8);
    run_layer(h1, h2, D1, D2, tid);
    __syncthreads();

    wait_stage(2, 10);
    // Layer 3 fused with group-sum (position perm stays within each group).
    const int lane = tid & 31;
    const int warp = tid >> 5;

    for (int g = 0; g < KCLS; g++) {
        float acc[ROWS];
#pragma unroll
        for (int r = 0; r < ROWS; r++) acc[r] = 0.f;
        {
            int mj = D1 + D2 + g * GRP + tid;     // GRP == NTHREADS
            NeuronIn n;
            fetch_neuron(h2, mj, n);
            float2 c01 = __half22float2(*reinterpret_cast<const __half2*>(&n.u01));
            float2 c23 = __half22float2(*reinterpret_cast<const __half2*>(&n.u23));
#pragma unroll
            for (int r = 0; r < 2; r++) {
                uint32_t ua = (r == 0) ? n.a.x : n.a.y;
                uint32_t ub = (r == 0) ? n.b.x : n.b.y;
                float2 a = __half22float2(*reinterpret_cast<const __half2*>(&ua));
                float2 b = __half22float2(*reinterpret_cast<const __half2*>(&ub));
                acc[2 * r + 0] = fmaf(fmaf(c23.y, b.x, c01.y), a.x, fmaf(c23.x, b.x, c01.x));
                acc[2 * r + 1] = fmaf(fmaf(c23.y, b.y, c01.y), a.y, fmaf(c23.x, b.y, c01.x));
            }
        }
#pragma unroll
        for (int r = 0; r < ROWS; r++) {
#pragma unroll
            for (int off = 16; off > 0; off >>= 1)
                acc[r] += __shfl_down_sync(0xffffffffu, acc[r], off);
        }
        if (lane == 0) {
#pragma unroll
            for (int r = 0; r < ROWS; r++)
                wacc[(g * NWARP + warp) * ROWS + r] = acc[r];
        }
    }
    __syncthreads();

    if (tid < KCLS * ROWS) {
        int g = tid / ROWS;
        int r = tid - g * ROWS;
        float s = 0.f;
#pragma unroll
        for (int w = 0; w < NWARP; w++)
            s += wacc[(g * NWARP + w) * ROWS + r];
        out[(size_t)(row0 + r) * KCLS + g] = s * (1.f / TAU);
    }
}

// -----------------------------------------------------------------------------

extern "C" void kernel_launch(void* const* d_in, const int* in_sizes, int n_in,
                              void* d_out, int out_size)
{
    (void)in_sizes; (void)n_in; (void)out_size;
    const float* x  = (const float*)d_in[0];
    const float* w1 = (const float*)d_in[1];
    const float* w2 = (const float*)d_in[2];
    const float* w3 = (const float*)d_in[3];
    const int* ia1 = (const int*)d_in[4];
    const int* ib1 = (const int*)d_in[5];
    const int* ia2 = (const int*)d_in[6];
    const int* ib2 = (const int*)d_in[7];
    const int* ia3 = (const int*)d_in[8];
    const int* ib3 = (const int*)d_in[9];
    float* out = (float*)d_out;

    precompute_kernel<<<(NNEUR + 255) / 256, 256>>>(w1, w2, w3, ia1, ib1, ia2, ib2, ia3, ib3);

    size_t smem = (size_t)(D0 + D1 + D2) * sizeof(uint2)
                + (size_t)(KCLS * NWARP * ROWS) * sizeof(float);   // 144,384 B
    cudaFuncSetAttribute(diff_logic_main, cudaFuncAttributeMaxDynamicSharedMemorySize, (int)smem);

    diff_logic_main<<<B_SZ / ROWS, NTHREADS, smem>>>(x, out);
}